// round 4
// baseline (speedup 1.0000x reference)
#include <cuda_runtime.h>
#include <cstdint>

// ---------------------------------------------------------------------------
// STFT round-trip == elementwise gain:
//   out[b,t] = wav[b,t] * (sum_f win[t_pad-256f]) / (EPS + sum_f sqw[t_pad-256f])
// because fb^T * pinv(SCALE*fb)^T = I/SCALE exactly (fb has full column rank),
// so the forward conv + pinv-synthesis is an exact identity up to the window
// envelope. Gain is periodic (period 256) except the first/last 256 samples
// of each row (3-frame coverage at the edges).
// ---------------------------------------------------------------------------

#define T_LEN   2097152u          // row length (2^21)
#define NBATCH  8
#define THREADS 256
#define BLOCKS  2048
#define GTOT    (BLOCKS * THREADS)   // 2^19 threads; 8 float4 vecs each = 2^22 vecs total
#define FMAX    8192                 // nF - 1

// Interior gain table, one entry per (t mod 256). 16B-aligned for float4 reads.
__device__ __align__(16) float g_int[256];

// ---- 1) Build the 256-entry interior gain table (all 4 frames valid) ------
__global__ void stft_setup_g(const float* __restrict__ sqw) {
    int m = threadIdx.x;                 // 0..255
    float num = 0.0f, den = 1e-9f;
#pragma unroll
    for (int j = 0; j < 4; j++) {
        float s = sqw[m + 256 * j];
        num += sqrtf(s);                 // win[k] = sqrt(win^2[k])
        den += s;
    }
    g_int[m] = num / den;
}

// ---- 2) Main streaming multiply (DRAM-bound) -------------------------------
// Thread layout: stride between a thread's vecs is GTOT float4s = 4*GTOT
// elements, which is ≡ 0 (mod 256), so each thread's 4-element phase within
// the 256-periodic gain is FIXED -> load its gains once into registers.
__global__ __launch_bounds__(THREADS) void stft_main(
    const ulonglong2* __restrict__ in,   // wav viewed as 16B vectors
    ulonglong2*       __restrict__ out)
{
    unsigned gt = blockIdx.x * THREADS + threadIdx.x;

    // phase of this thread's first element = (4*gt) & 255 -> float4 index gt & 63
    const float4 g = ((const float4*)g_int)[gt & 63u];
    unsigned long long g01, g23;
    asm("mov.b64 %0, {%1,%2};" : "=l"(g01) : "f"(g.x), "f"(g.y));
    asm("mov.b64 %0, {%1,%2};" : "=l"(g23) : "f"(g.z), "f"(g.w));

#pragma unroll
    for (int k = 0; k < 8; k++) {
        unsigned v = gt + (unsigned)k * (unsigned)GTOT;   // 8 * 2^19 = 2^22 vecs total
        ulonglong2 w = in[v];                             // LDG.E.128
        ulonglong2 r;
        asm("mul.rn.f32x2 %0, %1, %2;" : "=l"(r.x) : "l"(w.x), "l"(g01));
        asm("mul.rn.f32x2 %0, %1, %2;" : "=l"(r.y) : "l"(w.y), "l"(g23));
        out[v] = r;                                       // STG.E.128
    }
}

// ---- 3) Edge fixup: first/last 256 samples of each row (3 frames) ----------
__global__ void stft_fixup(const float* __restrict__ wav,
                           const float* __restrict__ sqw,
                           float*       __restrict__ out)
{
    unsigned b = blockIdx.x;             // 0..7
    unsigned j = threadIdx.x;            // 0..511
    unsigned t = (j < 256u) ? j : (T_LEN - 512u + j);

    unsigned tp    = t + 512u;           // position in padded signal
    int      fbase = (int)(tp >> 8);
    int      m     = (int)(tp & 255u);

    float num = 0.0f, den = 1e-9f;
#pragma unroll
    for (int jj = 0; jj < 4; jj++) {
        int f = fbase - jj;              // frame index contributing offset m+256*jj
        if (f >= 0 && f <= FMAX) {
            float s = sqw[m + 256 * jj];
            num += sqrtf(s);
            den += s;
        }
    }
    unsigned idx = b * T_LEN + t;
    out[idx] = wav[idx] * (num / den);
}

// ---------------------------------------------------------------------------
extern "C" void kernel_launch(void* const* d_in, const int* in_sizes, int n_in,
                              void* d_out, int out_size)
{
    const float* wav = (const float*)d_in[0];   // (8, 2097152) f32
    // d_in[1] = forward_basis, d_in[2] = inverse_basis: unused (identity folded out)
    const float* sqw = (const float*)d_in[3];   // (1024,) f32  = win^2
    float* out = (float*)d_out;

    stft_setup_g<<<1, 256>>>(sqw);
    stft_main<<<BLOCKS, THREADS>>>((const ulonglong2*)wav, (ulonglong2*)out);
    stft_fixup<<<NBATCH, 512>>>(wav, sqw, out);
    (void)in_sizes; (void)n_in; (void)out_size;
}